// round 16
// baseline (speedup 1.0000x reference)
#include <cuda_runtime.h>
#include <cuda_bf16.h>
#include <cuda_fp16.h>
#include <cstdint>
#include <math.h>

// Problem constants
#define NTOK 16384
#define DDIM 1024
#define HDIM 4096
#define NEXP 8
#define DOUT 4096
#define NSLOT (2 * NTOK)

// ---------------- scratch (no allocations allowed) ----------------
__device__ float g_wgp[DDIM * NEXP + NEXP];
__device__ int   g_cnt[NEXP];
__device__ int   g_base[NEXP];
__device__ int   g_bidx[NEXP * NTOK];
__device__ int2  g_tokE[NTOK];
__device__ int2  g_tokP[NTOK];
__device__ float2 g_tokW[NTOK];

// fp16 planes
__device__ uint16_t g_x16[(size_t)NTOK * DDIM];
__device__ uint16_t g_wi16[(size_t)DDIM * DDIM];
__device__ uint16_t g_h16[(size_t)NTOK * DDIM];
__device__ uint16_t g_he16[(size_t)NSLOT * HDIM];
__device__ uint16_t g_ys16[(size_t)NSLOT * DDIM];
__device__ uint16_t g_m16[(size_t)NTOK * DDIM];
__device__ uint16_t g_w1f[(size_t)NEXP * DDIM * HDIM];
__device__ uint16_t g_w2f[(size_t)NEXP * HDIM * DDIM];
__device__ uint16_t g_whf[(size_t)DDIM * DOUT];

// ---------------- helpers ----------------
static __device__ __forceinline__ uint32_t smem_u32(const void* p) {
    uint32_t a;
    asm("{ .reg .u64 t; cvta.to.shared.u64 t, %1; cvt.u32.u64 %0, t; }"
        : "=r"(a) : "l"(p));
    return a;
}
static __device__ __forceinline__ void cp_async16(uint32_t dst, const void* src, int srcBytes) {
    asm volatile("cp.async.cg.shared.global [%0], [%1], %2, %3;"
                 :: "r"(dst), "l"(src), "n"(16), "r"(srcBytes) : "memory");
}
#define CP_COMMIT() asm volatile("cp.async.commit_group;" ::: "memory")
#define CP_WAIT(n)  asm volatile("cp.async.wait_group %0;" :: "n"(n) : "memory")

#define MBAR_INIT(addr, cnt) \
    asm volatile("mbarrier.init.shared.b64 [%0], %1;" :: "r"(addr), "r"(cnt) : "memory")
#define MBAR_ARRIVE(addr) \
    asm volatile("mbarrier.arrive.shared.b64 _, [%0];" :: "r"(addr) : "memory")
#define MBAR_WAIT(addr, par) do {                                                   \
    uint32_t _m = (addr); uint32_t _p = (par); uint32_t _done;                      \
    asm volatile("{\n\t.reg .pred p;\n\t"                                           \
        "mbarrier.try_wait.parity.acquire.cta.shared::cta.b64 p, [%1], %2;\n\t"     \
        "selp.b32 %0, 1, 0, p;\n\t}" : "=r"(_done) : "r"(_m), "r"(_p) : "memory");  \
    if (!_done) {                                                                    \
        asm volatile("{\n\t.reg .pred P1;\n\t"                                      \
            "WL_%=:\n\t"                                                            \
            "mbarrier.try_wait.parity.acquire.cta.shared::cta.b64 P1, [%0], %1, 0x989680;\n\t" \
            "@P1 bra.uni WD_%=;\n\t"                                                \
            "bra.uni WL_%=;\n\t"                                                    \
            "WD_%=:\n\t}" :: "r"(_m), "r"(_p) : "memory");                          \
    }                                                                                \
} while (0)

static __device__ __forceinline__ void ldsm_x4(uint32_t (&r)[4], uint32_t addr) {
    asm volatile("ldmatrix.sync.aligned.m8n8.x4.shared.b16 {%0,%1,%2,%3}, [%4];"
                 : "=r"(r[0]), "=r"(r[1]), "=r"(r[2]), "=r"(r[3]) : "r"(addr));
}
static __device__ __forceinline__ void ldsm_x4_t(uint32_t (&r)[4], uint32_t addr) {
    asm volatile("ldmatrix.sync.aligned.m8n8.x4.trans.shared.b16 {%0,%1,%2,%3}, [%4];"
                 : "=r"(r[0]), "=r"(r[1]), "=r"(r[2]), "=r"(r[3]) : "r"(addr));
}
static __device__ __forceinline__ void mma_f16(float (&d)[4],
    uint32_t a0, uint32_t a1, uint32_t a2, uint32_t a3, uint32_t b0, uint32_t b1)
{
    asm volatile("mma.sync.aligned.m16n8k16.row.col.f32.f16.f16.f32 "
                 "{%0,%1,%2,%3}, {%4,%5,%6,%7}, {%8,%9}, {%0,%1,%2,%3};"
                 : "+f"(d[0]), "+f"(d[1]), "+f"(d[2]), "+f"(d[3])
                 : "r"(a0), "r"(a1), "r"(a2), "r"(a3), "r"(b0), "r"(b1));
}

// ---------------- small kernels ----------------
__global__ void zero_i_kernel(int* p, int n) {
    int i = blockIdx.x * blockDim.x + threadIdx.x;
    if (i < n) p[i] = 0;
}
__global__ void tohalf_kernel(const float* __restrict__ src,
                              uint16_t* __restrict__ dst, long long n4)
{
    long long i = blockIdx.x * (long long)blockDim.x + threadIdx.x;
    long long stride = (long long)gridDim.x * blockDim.x;
    for (; i < n4; i += stride) {
        float4 v = reinterpret_cast<const float4*>(src)[i];
        __half2 a = __floats2half2_rn(v.x, v.y);
        __half2 b = __floats2half2_rn(v.z, v.w);
        reinterpret_cast<uint2*>(dst)[i] =
            make_uint2(*reinterpret_cast<uint32_t*>(&a),
                       *reinterpret_cast<uint32_t*>(&b));
    }
}
__global__ void prefix_kernel(const int* __restrict__ cnt, int* __restrict__ base) {
    if (threadIdx.x == 0) {
        int s = 0;
#pragma unroll
        for (int e = 0; e < NEXP; e++) { base[e] = s; s += cnt[e]; }
    }
}
__global__ void __launch_bounds__(128)
combine_kernel(const uint16_t* __restrict__ ys16, const int* __restrict__ base,
               const int2* __restrict__ tokE, const int2* __restrict__ tokP,
               const float2* __restrict__ tokW, uint16_t* __restrict__ m16)
{
    const int t = blockIdx.x;
    int2 te = tokE[t];
    int2 tp = tokP[t];
    float2 tw = tokW[t];
    long long s0 = (long long)(base[te.x] + tp.x) * DDIM;
    long long s1 = (long long)(base[te.y] + tp.y) * DDIM;
    int c = threadIdx.x * 8;
    uint4 y0 = *reinterpret_cast<const uint4*>(ys16 + s0 + c);
    uint4 y1 = *reinterpret_cast<const uint4*>(ys16 + s1 + c);
    __half2 w0 = __float2half2_rn(tw.x);
    __half2 w1 = __float2half2_rn(tw.y);
    uint4 o;
    const __half2* p0 = reinterpret_cast<const __half2*>(&y0);
    const __half2* p1 = reinterpret_cast<const __half2*>(&y1);
    __half2* po = reinterpret_cast<__half2*>(&o);
#pragma unroll
    for (int j = 0; j < 4; j++)
        po[j] = __hfma2(w0, p0[j], __hmul2(w1, p1[j]));
    *reinterpret_cast<uint4*>(m16 + (long long)t * DDIM + c) = o;
}

// ---------------- Wg' = W_in @ W_gate (+ c = b_in @ W_gate), exact fp32 ----------------
__global__ void __launch_bounds__(256)
wgp_kernel(const float* __restrict__ W_in, const float* __restrict__ b_in,
           const float* __restrict__ Wg, float* __restrict__ wgp)
{
    __shared__ float sWg[DDIM * 9];
    const int tid = threadIdx.x;
    for (int i = tid; i < DDIM * NEXP; i += 256)
        sWg[(i >> 3) * 9 + (i & 7)] = Wg[i];
    __syncthreads();

    const int warp = tid >> 5;
    const int lane = tid & 31;
    const int d = blockIdx.x * 8 + warp;
    if (d > DDIM) return;

    const float* row = (d < DDIM) ? W_in + (long long)d * DDIM : b_in;

    float accv[NEXP];
#pragma unroll
    for (int e = 0; e < NEXP; e++) accv[e] = 0.f;
    for (int j = lane; j < DDIM; j += 32) {
        float v = row[j];
        const float* wr = &sWg[j * 9];
#pragma unroll
        for (int e = 0; e < NEXP; e++)
            accv[e] = fmaf(v, wr[e], accv[e]);
    }
#pragma unroll
    for (int e = 0; e < NEXP; e++) {
#pragma unroll
        for (int off = 16; off > 0; off >>= 1)
            accv[e] += __shfl_xor_sync(0xffffffffu, accv[e], off);
    }
    if (lane == 0) {
#pragma unroll
        for (int e = 0; e < NEXP; e++)
            wgp[d * NEXP + e] = accv[e];
    }
}

// ---------------- gating: exact fp32 logits from x ----------------
__global__ void __launch_bounds__(256)
gate_kernel(const float* __restrict__ x, const float* __restrict__ wgp,
            int* __restrict__ cnt, int* __restrict__ bidx,
            int2* __restrict__ tokE, int2* __restrict__ tokP,
            float2* __restrict__ tokW)
{
    __shared__ float sW[DDIM * 9];
    __shared__ float sc[NEXP];
    const int tid = threadIdx.x;
    for (int i = tid; i < DDIM * NEXP; i += 256)
        sW[(i >> 3) * 9 + (i & 7)] = wgp[i];
    if (tid < NEXP) sc[tid] = wgp[DDIM * NEXP + tid];
    __syncthreads();

    const int warp = tid >> 5;
    const int lane = tid & 31;
    const int token = blockIdx.x * 8 + warp;
    if (token >= NTOK) return;

    float accv[NEXP];
#pragma unroll
    for (int e = 0; e < NEXP; e++) accv[e] = 0.f;
    const float* xrow = x + (long long)token * DDIM;
    for (int d = lane; d < DDIM; d += 32) {
        float xv = xrow[d];
        const float* wr = &sW[d * 9];
#pragma unroll
        for (int e = 0; e < NEXP; e++)
            accv[e] = fmaf(xv, wr[e], accv[e]);
    }
#pragma unroll
    for (int e = 0; e < NEXP; e++) {
#pragma unroll
        for (int off = 16; off > 0; off >>= 1)
            accv[e] += __shfl_xor_sync(0xffffffffu, accv[e], off);
    }
    if (lane == 0) {
#pragma unroll
        for (int e = 0; e < NEXP; e++) accv[e] += sc[e];
        int i1 = 0; float l1 = accv[0];
#pragma unroll
        for (int e = 1; e < NEXP; e++)
            if (accv[e] > l1) { l1 = accv[e]; i1 = e; }
        int i2 = -1; float l2 = -3.0e38f;
#pragma unroll
        for (int e = 0; e < NEXP; e++)
            if (e != i1 && accv[e] > l2) { l2 = accv[e]; i2 = e; }
        float p2 = expf(l2 - l1);
        float w1 = 1.f / (1.f + p2);
        float w2 = p2 * w1;
        int p = atomicAdd(&cnt[i1], 1);
        bidx[i1 * NTOK + p] = token;
        int q = atomicAdd(&cnt[i2], 1);
        bidx[i2 * NTOK + q] = token;
        tokE[token] = make_int2(i1, i2);
        tokP[token] = make_int2(p, q);
        tokW[token] = make_float2(w1, w2);
    }
}

// ---------------- warp-specialized fp16 GEMM, software-pipelined fragments ----------------
// Tile 192x128, 448 threads: warps 0..11 consumers (3x4 of 64x32),
// warps 12..13 producers. CK=64, NB=4 buffers.
#define TM 192
#define GEMM_THREADS 448
#define GEMM_SMEM (1024 + 4 * 40960)

__global__ void __launch_bounds__(GEMM_THREADS, 1)
tc_gemm(const uint16_t* __restrict__ A_g, const uint16_t* __restrict__ B_g,
        size_t bStride,
        float* __restrict__ Cf, uint16_t* __restrict__ Oh,
        const float* __restrict__ bias,
        const int* __restrict__ gatherIdx,
        const int* __restrict__ cntPtr, const int* __restrict__ basePtr,
        int Mfix, int N, int K, int doRelu)
{
    extern __shared__ char smem[];

    constexpr int CK   = 64;
    constexpr int NB   = 4;
    constexpr uint32_t ARB  = 128;
    constexpr uint32_t BOFF = TM * ARB;           // 24576
    constexpr uint32_t BUFB = BOFF + 16384;       // 40960

    const int z = blockIdx.z;
    int M = cntPtr ? __ldg(cntPtr + z) : Mfix;
    const int obase = basePtr ? __ldg(basePtr + z) : 0;
    const int row0 = blockIdx.y * TM;
    if (row0 >= M) return;
    const int col0 = blockIdx.x * 128;

    const int tid  = threadIdx.x;
    const int lane = tid & 31;
    const int wid  = tid >> 5;

    const uint32_t smem_base = smem_u32(smem);
    const uint32_t mb_full  = smem_base;
    const uint32_t mb_empty = smem_base + 64;
    int* gRow_s = reinterpret_cast<int*>(smem + 128);
    const uint32_t tiles    = smem_base + 1024;

    const int* gIdx = gatherIdx ? gatherIdx + (size_t)z * NTOK : nullptr;

    if (tid == 0) {
#pragma unroll
        for (int b = 0; b < NB; b++) {
            MBAR_INIT(mb_full + b * 8, 64);
            MBAR_INIT(mb_empty + b * 8, 12);
        }
    }
    if (tid < TM) {
        int m = row0 + tid;
        gRow_s[tid] = (m < M) ? (gIdx ? gIdx[m] : obase + m) : -1;
    }
    __syncthreads();

    const uint16_t* B_e = B_g + (size_t)z * bStride;
    const int nchunk = K / CK;

    // =========== producers ===========
    if (wid >= 12) {
        const int ptid = tid - 384;
        const int rowBase = ptid >> 3;
        const int colA = ptid & 7;
        const uint32_t swA = (uint32_t)(colA ^ rowBase) << 4;
        int gr[24];
#pragma unroll
        for (int i = 0; i < 24; i++) gr[i] = gRow_s[rowBase + 8 * i];

        for (int c = 0; c < nchunk; c++) {
            int b = c % NB;
            if (c >= NB) MBAR_WAIT(mb_empty + b * 8, ((c - NB) / NB) & 1);
            int k0 = c * CK;
            uint32_t bufA = tiles + b * BUFB;
            uint32_t bufB = bufA + BOFF;
#pragma unroll
            for (int i = 0; i < 24; i++) {
                uint32_t d = bufA + (uint32_t)(rowBase + 8 * i) * ARB + swA;
                const uint16_t* s = (gr[i] >= 0)
                    ? A_g + (long long)gr[i] * K + k0 + colA * 8 : A_g;
                cp_async16(d, s, (gr[i] >= 0) ? 16 : 0);
            }
#pragma unroll
            for (int i = 0; i < 16; i++) {
                int u = ptid + 64 * i;
                int kr = u >> 4, un = u & 15;
                uint32_t d = bufB + kr * 256 + (((uint32_t)(un ^ (kr & 7))) << 4);
                cp_async16(d, B_e + (long long)(k0 + kr) * N + col0 + un * 8, 16);
            }
            CP_COMMIT();
            if (c >= 2) { CP_WAIT(2); MBAR_ARRIVE(mb_full + ((c - 2) % NB) * 8); }
        }
        CP_WAIT(1); MBAR_ARRIVE(mb_full + ((nchunk - 2) % NB) * 8);
        CP_WAIT(0); MBAR_ARRIVE(mb_full + ((nchunk - 1) % NB) * 8);
        return;
    }

    // =========== consumers ===========
    const int wm = wid >> 2;
    const int wn = wid & 3;

    const int rowA  = wm * 64 + (lane & 7) + ((lane >> 3) & 1) * 8;
    const int kbA   = (lane >> 4) & 1;
    const int swzA  = rowA & 7;
    const int kBld  = (lane & 7) + ((lane >> 3) & 1) * 8;
    const int nbB   = (lane >> 4) & 1;
    const int kswzB = kBld & 7;
    const int krot  = wid & 3;

    float acc[4][4][4];
#pragma unroll
    for (int mi = 0; mi < 4; mi++)
#pragma unroll
        for (int nj = 0; nj < 4; nj++)
#pragma unroll
            for (int q = 0; q < 4; q++) acc[mi][nj][q] = 0.f;

    uint32_t ah2[2][4][4], bh2[2][2][4];

    auto ldfrag = [&](int kk, uint32_t bufA, uint32_t bufB, int pb) {
#pragma unroll
        for (int j = 0; j < 2; j++) {
            int nchk = wn * 4 + j * 2 + nbB;
            uint32_t boff = (uint32_t)((kBld + kk * 16) * 256 +
                            ((nchk ^ kswzB) << 4));
            ldsm_x4_t(bh2[pb][j], bufB + boff);
        }
#pragma unroll
        for (int mi = 0; mi < 4; mi++) {
            uint32_t aoff = (uint32_t)((rowA + mi * 16) * ARB +
                            (((kk * 2 + kbA) ^ swzA) << 4));
            ldsm_x4(ah2[pb][mi], bufA + aoff);
        }
    };

    // prologue: wait chunk 0, load its first kstep fragments
    MBAR_WAIT(mb_full + 0, 0);
    {
        uint32_t bufA = tiles, bufB = tiles + BOFF;
        ldfrag(krot, bufA, bufB, 0);
    }

    int pb = 0;
    for (int c = 0; c < nchunk; c++) {
        const int b = c % NB;
        const uint32_t bufA = tiles + b * BUFB;
        const uint32_t bufB = bufA + BOFF;

#pragma unroll
        for (int ks = 0; ks < 4; ks++) {
            const int pn = pb ^ 1;
            if (ks < 3) {
                ldfrag(((ks + 1) + krot) & 3, bufA, bufB, pn);
            } else if (c + 1 < nchunk) {
                const int nb2 = (c + 1) % NB;
                MBAR_WAIT(mb_full + nb2 * 8, ((c + 1) / NB) & 1);
                ldfrag(krot, tiles + nb2 * BUFB, tiles + nb2 * BUFB + BOFF, pn);
                if (lane == 0) MBAR_ARRIVE(mb_empty + b * 8);
            } else {
                if (lane == 0) MBAR_ARRIVE(mb_empty + b * 8);
            }
#pragma unroll
            for (int mi = 0; mi < 4; mi++) {
#pragma unroll
                for (int nj = 0; nj < 4; nj++) {
                    int j = nj >> 1, q = (nj & 1) * 2;
                    mma_f16(acc[mi][nj],
                            ah2[pb][mi][0], ah2[pb][mi][1],
                            ah2[pb][mi][2], ah2[pb][mi][3],
                            bh2[pb][j][q], bh2[pb][j][q + 1]);
                }
            }
            pb ^= 1;
        }
    }

    // ---------------- epilogue ----------------
    const float* bias_e = bias ? bias + (size_t)z * N : nullptr;
    const int colBase = col0 + wn * 32 + (lane & 3) * 2;
#pragma unroll
    for (int mi = 0; mi < 4; mi++) {
        int r0 = row0 + wm * 64 + mi * 16 + (lane >> 2);
        int r1 = r0 + 8;
#pragma unroll
        for (int nj = 0; nj < 4; nj++) {
            int col = colBase + nj * 8;
            float b0 = bias_e ? bias_e[col] : 0.f;
            float b1 = bias_e ? bias_e[col + 1] : 0.f;
            float v00 = acc[mi][nj][0] + b0;
            float v01 = acc[mi][nj][1] + b1;
            float v10 = acc[mi][nj][2] + b0;
            float v11 = acc[mi][nj][3] + b1;
            if (doRelu) {
                v00 = fmaxf(v00, 0.f); v01 = fmaxf(v01, 0.f);
                v10 = fmaxf(v10, 0.f); v11 = fmaxf(v11, 0.f);
            }
            if (r0 < M) {
                long long o = (long long)(obase + r0) * N + col;
                if (Cf) { Cf[o] = v00; Cf[o + 1] = v01; }
                if (Oh) {
                    __half2 hv = __floats2half2_rn(v00, v01);
                    *reinterpret_cast<uint32_t*>(Oh + o) =
                        *reinterpret_cast<uint32_t*>(&hv);
                }
            }
            if (r1 < M) {
                long long o = (long long)(obase + r1) * N + col;
                if (Cf) { Cf[o] = v10; Cf[o + 1] = v11; }
                if (Oh) {
                    __half2 hv = __floats2half2_rn(v10, v11);
                    *reinterpret_cast<uint32_t*>(Oh + o) =
                        *reinterpret_cast<uint32_t*>(&hv);
                }
            }
        }
    }
}

#define GEMM_YT ((NTOK + TM - 1) / TM)

// ---------------- launch ----------------
extern "C" void kernel_launch(void* const* d_in, const int* in_sizes, int n_in,
                              void* d_out, int out_size)
{
    const float* x      = (const float*)d_in[0];
    const float* W_in   = (const float*)d_in[1];
    const float* b_in   = (const float*)d_in[2];
    const float* W_gate = (const float*)d_in[3];
    const float* W1     = (const float*)d_in[4];
    const float* b1     = (const float*)d_in[5];
    const float* W2     = (const float*)d_in[6];
    const float* b2     = (const float*)d_in[7];
    const float* W_head = (const float*)d_in[8];
    float* out = (float*)d_out;

    float *wgp_p;
    int *cnt_p, *base_p, *bidx_p;
    int2 *tokE_p, *tokP_p;
    float2 *tokW_p;
    uint16_t *x16, *wi16, *h16, *he16, *ys16, *m16, *w1f, *w2f, *whf;
    cudaGetSymbolAddress((void**)&wgp_p, g_wgp);
    cudaGetSymbolAddress((void**)&cnt_p, g_cnt);
    cudaGetSymbolAddress((void**)&base_p,g_base);
    cudaGetSymbolAddress((void**)&bidx_p,g_bidx);
    cudaGetSymbolAddress((void**)&tokE_p,g_tokE);
    cudaGetSymbolAddress((void**)&tokP_p,g_tokP);
    cudaGetSymbolAddress((void**)&tokW_p,g_tokW);
    cudaGetSymbolAddress((void**)&x16,  g_x16);
    cudaGetSymbolAddress((void**)&wi16, g_wi16);
    cudaGetSymbolAddress((void**)&h16,  g_h16);
    cudaGetSymbolAddress((void**)&he16, g_he16);
    cudaGetSymbolAddress((void**)&ys16, g_ys16);
    cudaGetSymbolAddress((void**)&m16,  g_m16);
    cudaGetSymbolAddress((void**)&w1f,  g_w1f);
    cudaGetSymbolAddress((void**)&w2f,  g_w2f);
    cudaGetSymbolAddress((void**)&whf,  g_whf);

    cudaFuncSetAttribute(tc_gemm,
                         cudaFuncAttributeMaxDynamicSharedMemorySize, GEMM_SMEM);

    tohalf_kernel<<<2048, 256>>>(x,    x16,  (long long)NTOK * DDIM / 4);      // 1
    tohalf_kernel<<<512,  256>>>(W_in, wi16, (long long)DDIM * DDIM / 4);      // 2
    zero_i_kernel<<<1, 32>>>(cnt_p, NEXP);                                     // 3

    // 4 (profiled): h16 = fp16(x16 @ wi16 + b_in)
    tc_gemm<<<dim3(DDIM / 128, GEMM_YT, 1), GEMM_THREADS, GEMM_SMEM>>>(
        x16, wi16, 0,
        nullptr, h16, b_in,
        nullptr, nullptr, nullptr, NTOK, DDIM, DDIM, 0);

    // exact fp32 gate path
    wgp_kernel<<<129, 256>>>(W_in, b_in, W_gate, wgp_p);
    gate_kernel<<<NTOK / 8, 256>>>(x, wgp_p, cnt_p, bidx_p, tokE_p, tokP_p, tokW_p);
    prefix_kernel<<<1, 32>>>(cnt_p, base_p);

    tohalf_kernel<<<4096, 256>>>(W1, w1f, (long long)NEXP * DDIM * HDIM / 4);
    tohalf_kernel<<<4096, 256>>>(W2, w2f, (long long)NEXP * HDIM * DDIM / 4);
    tohalf_kernel<<<1024, 256>>>(W_head, whf, (long long)DDIM * DOUT / 4);

    // up: he16[base[e]+m] = relu(h16[bidx[e,m]] @ W1f[e] + b1[e])
    tc_gemm<<<dim3(HDIM / 128, GEMM_YT, NEXP), GEMM_THREADS, GEMM_SMEM>>>(
        h16, w1f, (size_t)DDIM * HDIM,
        nullptr, he16, b1,
        bidx_p, cnt_p, base_p, 0, HDIM, DDIM, 1);

    // down: ys16[base[e]+m] = fp16(he16 @ W2f[e] + b2[e])
    tc_gemm<<<dim3(DDIM / 128, GEMM_YT, NEXP), GEMM_THREADS, GEMM_SMEM>>>(
        he16, w2f, (size_t)HDIM * DDIM,
        nullptr, ys16, b2,
        nullptr, cnt_p, base_p, 0, DDIM, HDIM, 0);

    // combine (fp16 in/out) -> m16 for head
    combine_kernel<<<NTOK, 128>>>(ys16, base_p, tokE_p, tokP_p, tokW_p, m16);

    // head: out = m16 @ whf
    tc_gemm<<<dim3(DOUT / 128, GEMM_YT, 1), GEMM_THREADS, GEMM_SMEM>>>(
        m16, whf, 0,
        out, nullptr, nullptr,
        nullptr, nullptr, nullptr, NTOK, DOUT, DDIM, 0);
}